// round 14
// baseline (speedup 1.0000x reference)
#include <cuda_runtime.h>
#include <math.h>
#include <stdint.h>

// Problem constants
#define BTOK   8192      // B*T
#define DMODEL 2048
#define NSLOT  4096
#define KTOP   32
#define DHID   1024

// Reference accumulation model (scheme g, fitted over 12 rounds):
// REMAINDER-FIRST kc=336 panels: ascending serial FMA chains over
// [0,32), [32,368), [368,704), ..., [1712,2048), each folded left-to-right
// into the running total with one FADD. Fold boundaries:
//   kend in {32, 368, 704, 1040, 1376, 1712, 2048}.
#define KC 336
#define PEEL 32

// Scratch (device globals — no allocation allowed in kernel_launch)
static __device__ float g_Q   [(size_t)BTOK * DMODEL];
static __device__ float g_sim [(size_t)BTOK * NSLOT];
static __device__ float g_retr[(size_t)BTOK * DMODEL];
static __device__ float g_R   [(size_t)BTOK * DMODEL];
static __device__ float g_h   [(size_t)BTOK * DHID];
static __device__ float g_w   [BTOK * KTOP];
static __device__ int   g_idx [BTOK * KTOP];

__device__ __forceinline__ float gelu_f(float v) {
    return 0.5f * v * (1.0f + erff(v * 0.70710678118654752440f));
}

// ---------------------------------------------------------------------------
// Reference-emulating NT SGEMM: C[M,N] = A[M,K] . B[N,K]^T  (scheme g):
// ascending-k serial FMA chains with folds at kend = 32 and every 336
// thereafter (32, 368, ..., 1712, 2048) — remainder peeled first.
// If SCALE, result divided (RN) by fp32 sqrt(2048) (monotone; doesn't affect
// top-k ordering, kept for faithfulness of sim values).
// BM=BN=64, BK=8, 256 threads, 4x4 micro-tile.
// ---------------------------------------------------------------------------
template<bool SCALE>
__global__ __launch_bounds__(256, 4)
void sgemm_nt_eigen(const float* __restrict__ A, int lda,
                    const float* __restrict__ B, int ldb,
                    float* __restrict__ C, int ldc, int K)
{
    const int BM = 64, BN = 64, BK = 8;
    __shared__ float As[BK][BM + 4];
    __shared__ float Bs[BK][BN + 4];

    const int tid  = threadIdx.x;
    const int bm   = blockIdx.y * BM;
    const int bn   = blockIdx.x * BN;
    const int lrow = tid >> 2;          // 0..63
    const int lcol = (tid & 3) * 2;     // 0,2,4,6

    const float* Ap = A + (size_t)(bm + lrow) * lda + lcol;
    const float* Bp = B + (size_t)(bn + lrow) * ldb + lcol;

    const int tx = tid & 15;            // n: tx*4
    const int ty = tid >> 4;            // m: ty*4

    float tot[4][4], chk[4][4];
    #pragma unroll
    for (int i = 0; i < 4; i++)
        #pragma unroll
        for (int j = 0; j < 4; j++) { tot[i][j] = 0.0f; chk[i][j] = 0.0f; }

    for (int k0 = 0; k0 < K; k0 += BK) {
        float2 a2 = *(const float2*)(Ap + k0);
        float2 b2 = *(const float2*)(Bp + k0);
        __syncthreads();
        As[lcol + 0][lrow] = a2.x; As[lcol + 1][lrow] = a2.y;
        Bs[lcol + 0][lrow] = b2.x; Bs[lcol + 1][lrow] = b2.y;
        __syncthreads();

        #pragma unroll
        for (int k = 0; k < BK; k++) {
            float ra[4], rb[4];
            *(float4*)ra = *(const float4*)&As[k][ty * 4];
            *(float4*)rb = *(const float4*)&Bs[k][tx * 4];
            #pragma unroll
            for (int i = 0; i < 4; i++)
                #pragma unroll
                for (int j = 0; j < 4; j++)
                    chk[i][j] = __fmaf_rn(ra[i], rb[j], chk[i][j]);
        }

        // remainder-first fold grid: kend = 32, 368, 704, ..., 1712, 2048
        int kend = k0 + BK;
        bool fold = (kend == PEEL) ||
                    (kend > PEEL && ((kend - PEEL) % KC) == 0);
        if (fold) {
            #pragma unroll
            for (int i = 0; i < 4; i++)
                #pragma unroll
                for (int j = 0; j < 4; j++) {
                    tot[i][j] = __fadd_rn(tot[i][j], chk[i][j]);
                    chk[i][j] = 0.0f;
                }
        }
    }

    const float sqrt_d = __fsqrt_rn(2048.0f);
    #pragma unroll
    for (int i = 0; i < 4; i++) {
        size_t row = (size_t)(bm + ty * 4 + i);
        float* crow = C + row * (size_t)ldc + bn + tx * 4;
        float4 v;
        float r[4];
        #pragma unroll
        for (int j = 0; j < 4; j++) {
            float f = tot[i][j];
            if (SCALE) f = __fdiv_rn(f, sqrt_d);
            r[j] = f;
        }
        v.x = r[0]; v.y = r[1]; v.z = r[2]; v.w = r[3];
        *(float4*)crow = v;
    }
}

// ---------------------------------------------------------------------------
// Fast NT SGEMM for the tolerance-insensitive GEMMs (out-proj, gate MLP).
// C = alpha*A.B^T (+C if ACCUM) (+bias,gelu if EPI==1). 128x128x8, 8x8 micro.
// ---------------------------------------------------------------------------
template<int EPI, bool ACCUM>
__global__ __launch_bounds__(256, 2)
void sgemm_nt(const float* __restrict__ A, int lda,
              const float* __restrict__ B, int ldb,
              float* __restrict__ C, int ldc,
              int K, float alpha, const float* __restrict__ bias)
{
    const int BM = 128, BN = 128, BK = 8;
    __shared__ float As[BK][BM];
    __shared__ float Bs[BK][BN];

    const int tid  = threadIdx.x;
    const int bm   = blockIdx.y * BM;
    const int bn   = blockIdx.x * BN;
    const int lrow = tid >> 1;
    const int lcol = (tid & 1) * 4;

    const float* Ap = A + (size_t)(bm + lrow) * lda + lcol;
    const float* Bp = B + (size_t)(bn + lrow) * ldb + lcol;

    const int tx = tid & 15;
    const int ty = tid >> 4;

    float acc[8][8];
    #pragma unroll
    for (int i = 0; i < 8; i++)
        #pragma unroll
        for (int j = 0; j < 8; j++) acc[i][j] = 0.0f;

    for (int k0 = 0; k0 < K; k0 += BK) {
        float4 a4 = *(const float4*)(Ap + k0);
        float4 b4 = *(const float4*)(Bp + k0);
        __syncthreads();
        As[lcol + 0][lrow] = a4.x; As[lcol + 1][lrow] = a4.y;
        As[lcol + 2][lrow] = a4.z; As[lcol + 3][lrow] = a4.w;
        Bs[lcol + 0][lrow] = b4.x; Bs[lcol + 1][lrow] = b4.y;
        Bs[lcol + 2][lrow] = b4.z; Bs[lcol + 3][lrow] = b4.w;
        __syncthreads();

        #pragma unroll
        for (int k = 0; k < BK; k++) {
            float ra[8], rb[8];
            *(float4*)(ra)     = *(const float4*)&As[k][ty * 8];
            *(float4*)(ra + 4) = *(const float4*)&As[k][ty * 8 + 4];
            *(float4*)(rb)     = *(const float4*)&Bs[k][tx * 8];
            *(float4*)(rb + 4) = *(const float4*)&Bs[k][tx * 8 + 4];
            #pragma unroll
            for (int i = 0; i < 8; i++)
                #pragma unroll
                for (int j = 0; j < 8; j++)
                    acc[i][j] = fmaf(ra[i], rb[j], acc[i][j]);
        }
    }

    #pragma unroll
    for (int i = 0; i < 8; i++) {
        size_t row = (size_t)(bm + ty * 8 + i);
        float* crow = C + row * (size_t)ldc + bn + tx * 8;
        #pragma unroll
        for (int j = 0; j < 8; j += 4) {
            float4 v;
            v.x = acc[i][j + 0] * alpha; v.y = acc[i][j + 1] * alpha;
            v.z = acc[i][j + 2] * alpha; v.w = acc[i][j + 3] * alpha;
            if (ACCUM) {
                float4 c0 = *(const float4*)(crow + j);
                v.x += c0.x; v.y += c0.y; v.z += c0.z; v.w += c0.w;
            }
            if (EPI == 1) {
                int col = bn + tx * 8 + j;
                v.x = gelu_f(v.x + bias[col + 0]);
                v.y = gelu_f(v.y + bias[col + 1]);
                v.z = gelu_f(v.z + bias[col + 2]);
                v.w = gelu_f(v.w + bias[col + 3]);
            }
            *(float4*)(crow + j) = v;
        }
    }
}

// ---------------------------------------------------------------------------
// Top-K (K=32), jax semantics: descending, ties -> lower index first.
// Then softmax over the 32. One block per row.
// ---------------------------------------------------------------------------
__global__ __launch_bounds__(256)
void topk_softmax(const float* __restrict__ sim,
                  float* __restrict__ w_out, int* __restrict__ idx_out,
                  float* __restrict__ dout_w, float* __restrict__ dout_idx)
{
    __shared__ float vals[NSLOT];
    __shared__ float rmax[256];
    __shared__ int   ridx[256];
    __shared__ float tv[KTOP];
    __shared__ int   ti[KTOP];

    const int t   = blockIdx.x;
    const int tid = threadIdx.x;
    const float* row = sim + (size_t)t * NSLOT;

    for (int i = tid; i < NSLOT; i += 256) vals[i] = row[i];
    __syncthreads();

    const float NEG_INF = __int_as_float(0xff800000);

    for (int it = 0; it < KTOP; it++) {
        float best = NEG_INF;
        int   bi   = 1 << 30;
        for (int i = tid; i < NSLOT; i += 256) {
            float v = vals[i];
            if (v > best) { best = v; bi = i; }
        }
        rmax[tid] = best; ridx[tid] = bi;
        __syncthreads();
        for (int st = 128; st > 0; st >>= 1) {
            if (tid < st) {
                float v2 = rmax[tid + st]; int i2 = ridx[tid + st];
                if (v2 > rmax[tid] || (v2 == rmax[tid] && i2 < ridx[tid])) {
                    rmax[tid] = v2; ridx[tid] = i2;
                }
            }
            __syncthreads();
        }
        if (tid == 0) {
            tv[it] = rmax[0];
            ti[it] = ridx[0];
            vals[ridx[0]] = NEG_INF;
        }
        __syncthreads();
    }

    if (tid < KTOP) {
        float e = expf(tv[tid] - tv[0]);
        float ssum = e;
        #pragma unroll
        for (int o = 16; o > 0; o >>= 1) ssum += __shfl_xor_sync(0xffffffffu, ssum, o);
        float w = e / ssum;
        size_t o = (size_t)t * KTOP + tid;
        w_out[o]   = w;
        idx_out[o] = ti[tid];
        if (dout_w)   dout_w[o]   = w;
        if (dout_idx) dout_idx[o] = (float)ti[tid];
    }
}

// ---------------------------------------------------------------------------
// retrieved[t,:] = sum_k w[t,k] * mem_values[idx[t,k], :]. One block/token.
// ---------------------------------------------------------------------------
__global__ __launch_bounds__(256)
void gather_wsum(const float* __restrict__ V,
                 const float* __restrict__ w, const int* __restrict__ idx,
                 float* __restrict__ outr)
{
    const int t   = blockIdx.x;
    const int tid = threadIdx.x;
    __shared__ float sw[KTOP];
    __shared__ int   si[KTOP];
    if (tid < KTOP) {
        sw[tid] = w[(size_t)t * KTOP + tid];
        si[tid] = idx[(size_t)t * KTOP + tid];
    }
    __syncthreads();

    float4 acc0 = make_float4(0.f, 0.f, 0.f, 0.f);
    float4 acc1 = make_float4(0.f, 0.f, 0.f, 0.f);
    #pragma unroll 4
    for (int k = 0; k < KTOP; k++) {
        const float4* vr = (const float4*)(V + (size_t)si[k] * DMODEL);
        float wk = sw[k];
        float4 v0 = vr[tid];
        float4 v1 = vr[tid + 256];
        acc0.x = fmaf(wk, v0.x, acc0.x); acc0.y = fmaf(wk, v0.y, acc0.y);
        acc0.z = fmaf(wk, v0.z, acc0.z); acc0.w = fmaf(wk, v0.w, acc0.w);
        acc1.x = fmaf(wk, v1.x, acc1.x); acc1.y = fmaf(wk, v1.y, acc1.y);
        acc1.z = fmaf(wk, v1.z, acc1.z); acc1.w = fmaf(wk, v1.w, acc1.w);
    }
    float4* orow = (float4*)(outr + (size_t)t * DMODEL);
    orow[tid]       = acc0;
    orow[tid + 256] = acc1;
}

// ---------------------------------------------------------------------------
// gate = sigmoid(h . wg2 + bg2); out = x + gate * R. One block/token.
// ---------------------------------------------------------------------------
__global__ __launch_bounds__(256)
void gate_output(const float* __restrict__ x, const float* __restrict__ R,
                 const float* __restrict__ H, const float* __restrict__ wg2,
                 const float* __restrict__ bg2, float* __restrict__ out)
{
    const int t   = blockIdx.x;
    const int tid = threadIdx.x;

    const float4* hr = (const float4*)(H + (size_t)t * DHID);
    const float4* gr = (const float4*)wg2;
    float4 hv = hr[tid];
    float4 gv = gr[tid];
    float p = hv.x * gv.x + hv.y * gv.y + hv.z * gv.z + hv.w * gv.w;

    __shared__ float red[256];
    red[tid] = p;
    __syncthreads();
    for (int st = 128; st > 0; st >>= 1) {
        if (tid < st) red[tid] += red[tid + st];
        __syncthreads();
    }
    __shared__ float gate_s;
    if (tid == 0) gate_s = 1.0f / (1.0f + expf(-(red[0] + bg2[0])));
    __syncthreads();
    float g = gate_s;

    const float4* xr = (const float4*)(x + (size_t)t * DMODEL);
    const float4* rr = (const float4*)(R + (size_t)t * DMODEL);
    float4* orow = (float4*)(out + (size_t)t * DMODEL);
    #pragma unroll
    for (int p4 = tid; p4 < DMODEL / 4; p4 += 256) {
        float4 xv = xr[p4], rv = rr[p4], ov;
        ov.x = xv.x + g * rv.x; ov.y = xv.y + g * rv.y;
        ov.z = xv.z + g * rv.z; ov.w = xv.w + g * rv.w;
        orow[p4] = ov;
    }
}

// ---------------------------------------------------------------------------
extern "C" void kernel_launch(void* const* d_in, const int* in_sizes, int n_in,
                              void* d_out, int out_size)
{
    const float* x   = (const float*)d_in[0];
    const float* mk  = (const float*)d_in[1];
    const float* mv  = (const float*)d_in[2];
    const float* wq  = (const float*)d_in[3];
    const float* wo  = (const float*)d_in[4];
    const float* wg1 = (const float*)d_in[5];
    const float* bg1 = (const float*)d_in[6];
    const float* wg2 = (const float*)d_in[7];
    const float* bg2 = (const float*)d_in[8];
    float* out = (float*)d_out;

    float *Q, *S, *RT, *R, *H, *W; int* IDX;
    cudaGetSymbolAddress((void**)&Q,   g_Q);
    cudaGetSymbolAddress((void**)&S,   g_sim);
    cudaGetSymbolAddress((void**)&RT,  g_retr);
    cudaGetSymbolAddress((void**)&R,   g_R);
    cudaGetSymbolAddress((void**)&H,   g_h);
    cudaGetSymbolAddress((void**)&W,   g_w);
    cudaGetSymbolAddress((void**)&IDX, g_idx);

    float* dout_w   = nullptr;
    float* dout_idx = nullptr;
    const size_t out_elems = (size_t)BTOK * DMODEL;
    const size_t aux_elems = (size_t)BTOK * KTOP;
    if ((size_t)out_size >= out_elems + 2 * aux_elems) {
        dout_w   = out + out_elems;
        dout_idx = out + out_elems + aux_elems;
    }

    dim3 blk(256);

    // 1) Q = X @ Wq^T  — scheme g (remainder-first 336-grid)
    sgemm_nt_eigen<false><<<dim3(DMODEL / 64, BTOK / 64), blk>>>(
        x, DMODEL, wq, DMODEL, Q, DMODEL, DMODEL);

    // 2) sim = (Q @ mem_keys^T) / sqrt(D)  — scheme g + RN divide
    sgemm_nt_eigen<true><<<dim3(NSLOT / 64, BTOK / 64), blk>>>(
        Q, DMODEL, mk, DMODEL, S, NSLOT, DMODEL);

    // 3) top-k + softmax
    topk_softmax<<<BTOK, 256>>>(S, W, IDX, dout_w, dout_idx);

    // 4) gather + weighted sum
    gather_wsum<<<BTOK, 256>>>(mv, W, IDX, RT);

    // 5) R = retrieved @ Wo^T  (fast path)
    sgemm_nt<0, false><<<dim3(DMODEL / 128, BTOK / 128), blk>>>(
        RT, DMODEL, wo, DMODEL, R, DMODEL, DMODEL, 1.0f, nullptr);

    // 6) h = gelu([x|R] @ Wg1^T + bg1), split over wg1 columns (fast path)
    sgemm_nt<0, false><<<dim3(DHID / 128, BTOK / 128), blk>>>(
        x, DMODEL, wg1, 2 * DMODEL, H, DHID, DMODEL, 1.0f, nullptr);
    sgemm_nt<1, true><<<dim3(DHID / 128, BTOK / 128), blk>>>(
        R, DMODEL, wg1 + DMODEL, 2 * DMODEL, H, DHID, DMODEL, 1.0f, bg1);

    // 7) gate + residual output
    gate_output<<<BTOK, 256>>>(x, R, H, wg2, bg2, out);
}

// round 15
// speedup vs baseline: 1.5593x; 1.5593x over previous
#include <cuda_runtime.h>
#include <cuda_bf16.h>
#include <mma.h>
#include <math.h>
#include <stdint.h>

using namespace nvcuda;

// Problem constants
#define BTOK   8192      // B*T
#define DMODEL 2048
#define NSLOT  4096
#define KTOP   32
#define DHID   1024

// Reference accumulation model (scheme g, VERIFIED PASSING in R14 — DO NOT
// CHANGE THE ARITHMETIC): remainder-first kc=336 panels: ascending serial FMA
// chains over [0,32),[32,368),...,[1712,2048), folded left-to-right.
// Fold boundaries: kend in {32, 368, 704, 1040, 1376, 1712, 2048}.
#define KC 336
#define PEEL 32

// Scratch (device globals — no allocation allowed in kernel_launch)
static __device__ float g_Q   [(size_t)BTOK * DMODEL];
static __device__ float g_sim [(size_t)BTOK * NSLOT];
static __device__ float g_retr[(size_t)BTOK * DMODEL];
static __device__ float g_R   [(size_t)BTOK * DMODEL];
static __device__ float g_h   [(size_t)BTOK * DHID];
static __device__ float g_w   [BTOK * KTOP];
static __device__ int   g_idx [BTOK * KTOP];
// bf16 staging for tensor-core GEMMs
static __device__ __nv_bfloat16 g_xRbf [(size_t)BTOK * (2 * DMODEL)];  // [x | R]
static __device__ __nv_bfloat16 g_rtbf [(size_t)BTOK * DMODEL];
static __device__ __nv_bfloat16 g_wobf [(size_t)DMODEL * DMODEL];
static __device__ __nv_bfloat16 g_wg1bf[(size_t)DHID * 2 * DMODEL];

__device__ __forceinline__ float gelu_f(float v) {
    return 0.5f * v * (1.0f + erff(v * 0.70710678118654752440f));
}

// ---------------------------------------------------------------------------
// Exact (reference-emulating) NT SGEMM, v2 tile shape for higher FMA density.
// C[M,N] = A[M,K].B[N,K]^T; per-element arithmetic BIT-IDENTICAL to R14:
// ascending-k serial FMA chain per output, folds at kend = 32 + n*336.
// BM=128, BN=64, BK=8, 256 threads, 8x4 micro-tile.
// If SCALE, result divided (RN) by fp32 sqrt(2048).
// ---------------------------------------------------------------------------
template<bool SCALE>
__global__ __launch_bounds__(256, 2)
void sgemm_nt_exact2(const float* __restrict__ A, int lda,
                     const float* __restrict__ B, int ldb,
                     float* __restrict__ C, int ldc, int K)
{
    const int BM = 128, BN = 64, BK = 8;
    __shared__ float As[BK][BM + 4];
    __shared__ float Bs[BK][BN + 4];

    const int tid = threadIdx.x;
    const int bm  = blockIdx.y * BM;
    const int bn  = blockIdx.x * BN;
    const int lrA = tid >> 1;           // 0..127
    const int lcA = (tid & 1) * 4;      // 0,4
    const int lrB = tid >> 2;           // 0..63
    const int lcB = (tid & 3) * 2;      // 0,2,4,6

    const float* Ap = A + (size_t)(bm + lrA) * lda + lcA;
    const float* Bp = B + (size_t)(bn + lrB) * ldb + lcB;

    const int tx = tid & 15;            // n: tx*4  (0..60)
    const int ty = tid >> 4;            // m: ty*8  (0..120)

    float tot[8][4], chk[8][4];
    #pragma unroll
    for (int i = 0; i < 8; i++)
        #pragma unroll
        for (int j = 0; j < 4; j++) { tot[i][j] = 0.0f; chk[i][j] = 0.0f; }

    for (int k0 = 0; k0 < K; k0 += BK) {
        float4 a4 = *(const float4*)(Ap + k0);
        float2 b2 = *(const float2*)(Bp + k0);
        __syncthreads();
        As[lcA + 0][lrA] = a4.x; As[lcA + 1][lrA] = a4.y;
        As[lcA + 2][lrA] = a4.z; As[lcA + 3][lrA] = a4.w;
        Bs[lcB + 0][lrB] = b2.x; Bs[lcB + 1][lrB] = b2.y;
        __syncthreads();

        #pragma unroll
        for (int k = 0; k < BK; k++) {
            float ra[8], rb[4];
            *(float4*)(ra)     = *(const float4*)&As[k][ty * 8];
            *(float4*)(ra + 4) = *(const float4*)&As[k][ty * 8 + 4];
            *(float4*)(rb)     = *(const float4*)&Bs[k][tx * 4];
            #pragma unroll
            for (int i = 0; i < 8; i++)
                #pragma unroll
                for (int j = 0; j < 4; j++)
                    chk[i][j] = __fmaf_rn(ra[i], rb[j], chk[i][j]);
        }

        // remainder-first fold grid: kend = 32, 368, 704, ..., 1712, 2048
        int kend = k0 + BK;
        bool fold = (kend == PEEL) ||
                    (kend > PEEL && ((kend - PEEL) % KC) == 0);
        if (fold) {
            #pragma unroll
            for (int i = 0; i < 8; i++)
                #pragma unroll
                for (int j = 0; j < 4; j++) {
                    tot[i][j] = __fadd_rn(tot[i][j], chk[i][j]);
                    chk[i][j] = 0.0f;
                }
        }
    }

    const float sqrt_d = __fsqrt_rn(2048.0f);
    #pragma unroll
    for (int i = 0; i < 8; i++) {
        size_t row = (size_t)(bm + ty * 8 + i);
        float* crow = C + row * (size_t)ldc + bn + tx * 4;
        float4 v;
        float f0 = tot[i][0], f1 = tot[i][1], f2 = tot[i][2], f3 = tot[i][3];
        if (SCALE) {
            f0 = __fdiv_rn(f0, sqrt_d); f1 = __fdiv_rn(f1, sqrt_d);
            f2 = __fdiv_rn(f2, sqrt_d); f3 = __fdiv_rn(f3, sqrt_d);
        }
        v.x = f0; v.y = f1; v.z = f2; v.w = f3;
        *(float4*)crow = v;
    }
}

// ---------------------------------------------------------------------------
// fp32 -> bf16 2D conversion (row-major, independent strides).
// ---------------------------------------------------------------------------
__global__ void f32_to_bf16_2d(const float* __restrict__ src, int sld,
                               __nv_bfloat16* __restrict__ dst, int dld,
                               int rows, int cols)
{
    int idx = blockIdx.x * blockDim.x + threadIdx.x;
    int total = rows * (cols >> 2);
    if (idx >= total) return;
    int row = idx / (cols >> 2);
    int c4  = (idx - row * (cols >> 2)) << 2;
    float4 v = *(const float4*)(src + (size_t)row * sld + c4);
    __nv_bfloat162 p0 = __floats2bfloat162_rn(v.x, v.y);
    __nv_bfloat162 p1 = __floats2bfloat162_rn(v.z, v.w);
    __nv_bfloat16* d = dst + (size_t)row * dld + c4;
    *(__nv_bfloat162*)(d)     = p0;
    *(__nv_bfloat162*)(d + 2) = p1;
}

// ---------------------------------------------------------------------------
// bf16 NT GEMM via WMMA (tensor cores): C[M,N] fp32 = A[M,K] . B[N,K]^T.
// 128x128 block tile, BK=32, 8 warps (4x2), each warp 32x64 (2x4 fragments).
// ---------------------------------------------------------------------------
#define TCM 128
#define TCN 128
#define TCK 32

__global__ __launch_bounds__(256, 2)
void wmma_gemm_nt(const __nv_bfloat16* __restrict__ A, int lda,
                  const __nv_bfloat16* __restrict__ B, int ldb,
                  float* __restrict__ C, int ldc, int K)
{
    __shared__ __nv_bfloat16 As[TCM][TCK + 8];
    __shared__ __nv_bfloat16 Bs[TCN][TCK + 8];

    const int tid  = threadIdx.x;
    const int warp = tid >> 5;
    const int wm   = warp >> 1;       // 0..3 -> 32-row slab
    const int wn   = warp & 1;        // 0..1 -> 64-col slab
    const int bm   = blockIdx.y * TCM;
    const int bn   = blockIdx.x * TCN;

    const int lr = tid >> 1;          // 0..127
    const int lc = (tid & 1) * 16;    // 0 or 16

    wmma::fragment<wmma::accumulator, 16, 16, 16, float> acc[2][4];
    #pragma unroll
    for (int i = 0; i < 2; i++)
        #pragma unroll
        for (int j = 0; j < 4; j++) wmma::fill_fragment(acc[i][j], 0.0f);

    for (int k0 = 0; k0 < K; k0 += TCK) {
        const float4* asrc = (const float4*)(A + (size_t)(bm + lr) * lda + k0 + lc);
        const float4* bsrc = (const float4*)(B + (size_t)(bn + lr) * ldb + k0 + lc);
        float4 av0 = asrc[0], av1 = asrc[1];
        float4 bv0 = bsrc[0], bv1 = bsrc[1];
        __syncthreads();
        *(float4*)&As[lr][lc]     = av0;
        *(float4*)&As[lr][lc + 8] = av1;
        *(float4*)&Bs[lr][lc]     = bv0;
        *(float4*)&Bs[lr][lc + 8] = bv1;
        __syncthreads();

        #pragma unroll
        for (int kk = 0; kk < TCK; kk += 16) {
            wmma::fragment<wmma::matrix_a, 16, 16, 16, __nv_bfloat16, wmma::row_major> af[2];
            wmma::fragment<wmma::matrix_b, 16, 16, 16, __nv_bfloat16, wmma::col_major> bf[4];
            #pragma unroll
            for (int i = 0; i < 2; i++)
                wmma::load_matrix_sync(af[i], &As[wm * 32 + i * 16][kk], TCK + 8);
            #pragma unroll
            for (int j = 0; j < 4; j++)
                wmma::load_matrix_sync(bf[j], &Bs[wn * 64 + j * 16][kk], TCK + 8);
            #pragma unroll
            for (int i = 0; i < 2; i++)
                #pragma unroll
                for (int j = 0; j < 4; j++)
                    wmma::mma_sync(acc[i][j], af[i], bf[j], acc[i][j]);
        }
    }

    #pragma unroll
    for (int i = 0; i < 2; i++)
        #pragma unroll
        for (int j = 0; j < 4; j++)
            wmma::store_matrix_sync(
                &C[(size_t)(bm + wm * 32 + i * 16) * ldc + bn + wn * 64 + j * 16],
                acc[i][j], ldc, wmma::mem_row_major);
}

// ---------------------------------------------------------------------------
// H = gelu(H + bias[col]) elementwise over [BTOK, DHID].
// ---------------------------------------------------------------------------
__global__ void bias_gelu(float* __restrict__ H, const float* __restrict__ bias)
{
    int idx = blockIdx.x * blockDim.x + threadIdx.x;   // quad index
    int col4 = (idx & (DHID / 4 - 1)) * 4;
    size_t off = (size_t)idx * 4;
    float4 v = *(float4*)(H + off);
    v.x = gelu_f(v.x + bias[col4 + 0]);
    v.y = gelu_f(v.y + bias[col4 + 1]);
    v.z = gelu_f(v.z + bias[col4 + 2]);
    v.w = gelu_f(v.w + bias[col4 + 3]);
    *(float4*)(H + off) = v;
}

// ---------------------------------------------------------------------------
// Top-K (K=32), jax semantics. One block per row. (unchanged from R14)
// ---------------------------------------------------------------------------
__global__ __launch_bounds__(256)
void topk_softmax(const float* __restrict__ sim,
                  float* __restrict__ w_out, int* __restrict__ idx_out,
                  float* __restrict__ dout_w, float* __restrict__ dout_idx)
{
    __shared__ float vals[NSLOT];
    __shared__ float rmax[256];
    __shared__ int   ridx[256];
    __shared__ float tv[KTOP];
    __shared__ int   ti[KTOP];

    const int t   = blockIdx.x;
    const int tid = threadIdx.x;
    const float* row = sim + (size_t)t * NSLOT;

    for (int i = tid; i < NSLOT; i += 256) vals[i] = row[i];
    __syncthreads();

    const float NEG_INF = __int_as_float(0xff800000);

    for (int it = 0; it < KTOP; it++) {
        float best = NEG_INF;
        int   bi   = 1 << 30;
        for (int i = tid; i < NSLOT; i += 256) {
            float v = vals[i];
            if (v > best) { best = v; bi = i; }
        }
        rmax[tid] = best; ridx[tid] = bi;
        __syncthreads();
        for (int st = 128; st > 0; st >>= 1) {
            if (tid < st) {
                float v2 = rmax[tid + st]; int i2 = ridx[tid + st];
                if (v2 > rmax[tid] || (v2 == rmax[tid] && i2 < ridx[tid])) {
                    rmax[tid] = v2; ridx[tid] = i2;
                }
            }
            __syncthreads();
        }
        if (tid == 0) {
            tv[it] = rmax[0];
            ti[it] = ridx[0];
            vals[ridx[0]] = NEG_INF;
        }
        __syncthreads();
    }

    if (tid < KTOP) {
        float e = expf(tv[tid] - tv[0]);
        float ssum = e;
        #pragma unroll
        for (int o = 16; o > 0; o >>= 1) ssum += __shfl_xor_sync(0xffffffffu, ssum, o);
        float w = e / ssum;
        size_t o = (size_t)t * KTOP + tid;
        w_out[o]   = w;
        idx_out[o] = ti[tid];
        if (dout_w)   dout_w[o]   = w;
        if (dout_idx) dout_idx[o] = (float)ti[tid];
    }
}

// ---------------------------------------------------------------------------
// retrieved[t,:] = sum_k w[t,k] * mem_values[idx[t,k], :]. One block/token.
// ---------------------------------------------------------------------------
__global__ __launch_bounds__(256)
void gather_wsum(const float* __restrict__ V,
                 const float* __restrict__ w, const int* __restrict__ idx,
                 float* __restrict__ outr)
{
    const int t   = blockIdx.x;
    const int tid = threadIdx.x;
    __shared__ float sw[KTOP];
    __shared__ int   si[KTOP];
    if (tid < KTOP) {
        sw[tid] = w[(size_t)t * KTOP + tid];
        si[tid] = idx[(size_t)t * KTOP + tid];
    }
    __syncthreads();

    float4 acc0 = make_float4(0.f, 0.f, 0.f, 0.f);
    float4 acc1 = make_float4(0.f, 0.f, 0.f, 0.f);
    #pragma unroll 4
    for (int k = 0; k < KTOP; k++) {
        const float4* vr = (const float4*)(V + (size_t)si[k] * DMODEL);
        float wk = sw[k];
        float4 v0 = vr[tid];
        float4 v1 = vr[tid + 256];
        acc0.x = fmaf(wk, v0.x, acc0.x); acc0.y = fmaf(wk, v0.y, acc0.y);
        acc0.z = fmaf(wk, v0.z, acc0.z); acc0.w = fmaf(wk, v0.w, acc0.w);
        acc1.x = fmaf(wk, v1.x, acc1.x); acc1.y = fmaf(wk, v1.y, acc1.y);
        acc1.z = fmaf(wk, v1.z, acc1.z); acc1.w = fmaf(wk, v1.w, acc1.w);
    }
    float4* orow = (float4*)(outr + (size_t)t * DMODEL);
    orow[tid]       = acc0;
    orow[tid + 256] = acc1;
}

// ---------------------------------------------------------------------------
// gate = sigmoid(h . wg2 + bg2); out = x + gate * R. One block/token.
// ---------------------------------------------------------------------------
__global__ __launch_bounds__(256)
void gate_output(const float* __restrict__ x, const float* __restrict__ R,
                 const float* __restrict__ H, const float* __restrict__ wg2,
                 const float* __restrict__ bg2, float* __restrict__ out)
{
    const int t   = blockIdx.x;
    const int tid = threadIdx.x;

    const float4* hr = (const float4*)(H + (size_t)t * DHID);
    const float4* gr = (const float4*)wg2;
    float4 hv = hr[tid];
    float4 gv = gr[tid];
    float p = hv.x * gv.x + hv.y * gv.y + hv.z * gv.z + hv.w * gv.w;

    __shared__ float red[256];
    red[tid] = p;
    __syncthreads();
    for (int st = 128; st > 0; st >>= 1) {
        if (tid < st) red[tid] += red[tid + st];
        __syncthreads();
    }
    __shared__ float gate_s;
    if (tid == 0) gate_s = 1.0f / (1.0f + expf(-(red[0] + bg2[0])));
    __syncthreads();
    float g = gate_s;

    const float4* xr = (const float4*)(x + (size_t)t * DMODEL);
    const float4* rr = (const float4*)(R + (size_t)t * DMODEL);
    float4* orow = (float4*)(out + (size_t)t * DMODEL);
    #pragma unroll
    for (int p4 = tid; p4 < DMODEL / 4; p4 += 256) {
        float4 xv = xr[p4], rv = rr[p4], ov;
        ov.x = xv.x + g * rv.x; ov.y = xv.y + g * rv.y;
        ov.z = xv.z + g * rv.z; ov.w = xv.w + g * rv.w;
        orow[p4] = ov;
    }
}

// ---------------------------------------------------------------------------
extern "C" void kernel_launch(void* const* d_in, const int* in_sizes, int n_in,
                              void* d_out, int out_size)
{
    const float* x   = (const float*)d_in[0];
    const float* mk  = (const float*)d_in[1];
    const float* mv  = (const float*)d_in[2];
    const float* wq  = (const float*)d_in[3];
    const float* wo  = (const float*)d_in[4];
    const float* wg1 = (const float*)d_in[5];
    const float* bg1 = (const float*)d_in[6];
    const float* wg2 = (const float*)d_in[7];
    const float* bg2 = (const float*)d_in[8];
    float* out = (float*)d_out;

    float *Q, *S, *RT, *R, *H, *W; int* IDX;
    __nv_bfloat16 *XRB, *RTB, *WOB, *WG1B;
    cudaGetSymbolAddress((void**)&Q,    g_Q);
    cudaGetSymbolAddress((void**)&S,    g_sim);
    cudaGetSymbolAddress((void**)&RT,   g_retr);
    cudaGetSymbolAddress((void**)&R,    g_R);
    cudaGetSymbolAddress((void**)&H,    g_h);
    cudaGetSymbolAddress((void**)&W,    g_w);
    cudaGetSymbolAddress((void**)&IDX,  g_idx);
    cudaGetSymbolAddress((void**)&XRB,  g_xRbf);
    cudaGetSymbolAddress((void**)&RTB,  g_rtbf);
    cudaGetSymbolAddress((void**)&WOB,  g_wobf);
    cudaGetSymbolAddress((void**)&WG1B, g_wg1bf);

    float* dout_w   = nullptr;
    float* dout_idx = nullptr;
    const size_t out_elems = (size_t)BTOK * DMODEL;
    const size_t aux_elems = (size_t)BTOK * KTOP;
    if ((size_t)out_size >= out_elems + 2 * aux_elems) {
        dout_w   = out + out_elems;
        dout_idx = out + out_elems + aux_elems;
    }

    dim3 blk(256);

    // weight converts (cheap; inside graph each replay)
    {
        int totw = DMODEL * DMODEL / 4;
        f32_to_bf16_2d<<<(totw + 255) / 256, blk>>>(wo, DMODEL, WOB, DMODEL,
                                                    DMODEL, DMODEL);
        int totg = DHID * 2 * DMODEL / 4;
        f32_to_bf16_2d<<<(totg + 255) / 256, blk>>>(wg1, 2 * DMODEL, WG1B,
                                                    2 * DMODEL, DHID, 2 * DMODEL);
        int totx = BTOK * DMODEL / 4;
        f32_to_bf16_2d<<<(totx + 255) / 256, blk>>>(x, DMODEL, XRB, 2 * DMODEL,
                                                    BTOK, DMODEL);
    }

    // 1) Q = X @ Wq^T  — scheme g (BIT-EXACT, verified)
    sgemm_nt_exact2<false><<<dim3(DMODEL / 64, BTOK / 128), blk>>>(
        x, DMODEL, wq, DMODEL, Q, DMODEL, DMODEL);

    // 2) sim = (Q @ mem_keys^T) / sqrt(D)  — scheme g + RN divide
    sgemm_nt_exact2<true><<<dim3(NSLOT / 64, BTOK / 128), blk>>>(
        Q, DMODEL, mk, DMODEL, S, NSLOT, DMODEL);

    // 3) top-k + softmax
    topk_softmax<<<BTOK, 256>>>(S, W, IDX, dout_w, dout_idx);

    // 4) gather + weighted sum
    gather_wsum<<<BTOK, 256>>>(mv, W, IDX, RT);

    // 5) R = retrieved @ Wo^T  — bf16 tensor cores
    {
        int tot = BTOK * DMODEL / 4;
        f32_to_bf16_2d<<<(tot + 255) / 256, blk>>>(RT, DMODEL, RTB, DMODEL,
                                                   BTOK, DMODEL);
        wmma_gemm_nt<<<dim3(DMODEL / TCN, BTOK / TCM), blk>>>(
            RTB, DMODEL, WOB, DMODEL, R, DMODEL, DMODEL);
    }

    // 6) h = gelu([x|R] @ Wg1^T + bg1) — single K=4096 bf16 GEMM
    {
        int tot = BTOK * DMODEL / 4;
        f32_to_bf16_2d<<<(tot + 255) / 256, blk>>>(R, DMODEL, XRB + DMODEL,
                                                   2 * DMODEL, BTOK, DMODEL);
        wmma_gemm_nt<<<dim3(DHID / TCN, BTOK / TCM), blk>>>(
            XRB, 2 * DMODEL, WG1B, 2 * DMODEL, H, DHID, 2 * DMODEL);
        int toth = BTOK * DHID / 4;
        bias_gelu<<<(toth + 255) / 256, blk>>>(H, bg1);
    }

    // 7) gate + residual output
    gate_output<<<BTOK, 256>>>(x, R, H, wg2, bg2, out);
}

// round 16
// speedup vs baseline: 1.9556x; 1.2541x over previous
#include <cuda_runtime.h>
#include <cuda_bf16.h>
#include <mma.h>
#include <math.h>
#include <stdint.h>

using namespace nvcuda;

// Problem constants
#define BTOK   8192      // B*T
#define DMODEL 2048
#define NSLOT  4096
#define KTOP   32
#define NCAND  64        // candidate set size (true top-32 margin ~90 sigma)
#define DHID   1024

// Reference accumulation (scheme g, VERIFIED): remainder-first kc=336 panels,
// ascending serial FMA chains, folds at kend in {32,368,704,1040,1376,1712,2048}.
#define KC 336
#define PEEL 32

// Scratch (device globals)
static __device__ float g_Q   [(size_t)BTOK * DMODEL];
static __device__ float g_sim [(size_t)BTOK * NSLOT];      // approx sim (bf16 TC)
static __device__ float g_retr[(size_t)BTOK * DMODEL];
static __device__ float g_R   [(size_t)BTOK * DMODEL];
static __device__ float g_h   [(size_t)BTOK * DHID];
static __device__ float g_w   [BTOK * KTOP];
static __device__ int   g_idx [BTOK * KTOP];
static __device__ int   g_c64 [(size_t)BTOK * NCAND];      // candidate slots
// bf16 staging
static __device__ __nv_bfloat16 g_xRbf [(size_t)BTOK * (2 * DMODEL)];  // [x | R]
static __device__ __nv_bfloat16 g_rtbf [(size_t)BTOK * DMODEL];
static __device__ __nv_bfloat16 g_qbf  [(size_t)BTOK * DMODEL];
static __device__ __nv_bfloat16 g_mkbf [(size_t)NSLOT * DMODEL];
static __device__ __nv_bfloat16 g_wobf [(size_t)DMODEL * DMODEL];
static __device__ __nv_bfloat16 g_wg1bf[(size_t)DHID * 2 * DMODEL];

__device__ __forceinline__ float gelu_f(float v) {
    return 0.5f * v * (1.0f + erff(v * 0.70710678118654752440f));
}

// ---------------------------------------------------------------------------
// Exact (scheme g) NT SGEMM — used for Q only. BIT-IDENTICAL arithmetic.
// BM=128, BN=64, BK=8, 256 threads, 8x4 micro-tile.
// ---------------------------------------------------------------------------
__global__ __launch_bounds__(256, 2)
void sgemm_nt_exact2(const float* __restrict__ A, int lda,
                     const float* __restrict__ B, int ldb,
                     float* __restrict__ C, int ldc, int K)
{
    const int BM = 128, BN = 64, BK = 8;
    __shared__ float As[BK][BM + 4];
    __shared__ float Bs[BK][BN + 4];

    const int tid = threadIdx.x;
    const int bm  = blockIdx.y * BM;
    const int bn  = blockIdx.x * BN;
    const int lrA = tid >> 1;
    const int lcA = (tid & 1) * 4;
    const int lrB = tid >> 2;
    const int lcB = (tid & 3) * 2;

    const float* Ap = A + (size_t)(bm + lrA) * lda + lcA;
    const float* Bp = B + (size_t)(bn + lrB) * ldb + lcB;

    const int tx = tid & 15;
    const int ty = tid >> 4;

    float tot[8][4], chk[8][4];
    #pragma unroll
    for (int i = 0; i < 8; i++)
        #pragma unroll
        for (int j = 0; j < 4; j++) { tot[i][j] = 0.0f; chk[i][j] = 0.0f; }

    for (int k0 = 0; k0 < K; k0 += BK) {
        float4 a4 = *(const float4*)(Ap + k0);
        float2 b2 = *(const float2*)(Bp + k0);
        __syncthreads();
        As[lcA + 0][lrA] = a4.x; As[lcA + 1][lrA] = a4.y;
        As[lcA + 2][lrA] = a4.z; As[lcA + 3][lrA] = a4.w;
        Bs[lcB + 0][lrB] = b2.x; Bs[lcB + 1][lrB] = b2.y;
        __syncthreads();

        #pragma unroll
        for (int k = 0; k < BK; k++) {
            float ra[8], rb[4];
            *(float4*)(ra)     = *(const float4*)&As[k][ty * 8];
            *(float4*)(ra + 4) = *(const float4*)&As[k][ty * 8 + 4];
            *(float4*)(rb)     = *(const float4*)&Bs[k][tx * 4];
            #pragma unroll
            for (int i = 0; i < 8; i++)
                #pragma unroll
                for (int j = 0; j < 4; j++)
                    chk[i][j] = __fmaf_rn(ra[i], rb[j], chk[i][j]);
        }

        int kend = k0 + BK;
        bool fold = (kend == PEEL) ||
                    (kend > PEEL && ((kend - PEEL) % KC) == 0);
        if (fold) {
            #pragma unroll
            for (int i = 0; i < 8; i++)
                #pragma unroll
                for (int j = 0; j < 4; j++) {
                    tot[i][j] = __fadd_rn(tot[i][j], chk[i][j]);
                    chk[i][j] = 0.0f;
                }
        }
    }

    #pragma unroll
    for (int i = 0; i < 8; i++) {
        size_t row = (size_t)(bm + ty * 8 + i);
        float4 v;
        v.x = tot[i][0]; v.y = tot[i][1]; v.z = tot[i][2]; v.w = tot[i][3];
        *(float4*)(C + row * (size_t)ldc + bn + tx * 4) = v;
    }
}

// ---------------------------------------------------------------------------
// fp32 -> bf16 2D conversion.
// ---------------------------------------------------------------------------
__global__ void f32_to_bf16_2d(const float* __restrict__ src, int sld,
                               __nv_bfloat16* __restrict__ dst, int dld,
                               int rows, int cols)
{
    int idx = blockIdx.x * blockDim.x + threadIdx.x;
    int total = rows * (cols >> 2);
    if (idx >= total) return;
    int row = idx / (cols >> 2);
    int c4  = (idx - row * (cols >> 2)) << 2;
    float4 v = *(const float4*)(src + (size_t)row * sld + c4);
    __nv_bfloat162 p0 = __floats2bfloat162_rn(v.x, v.y);
    __nv_bfloat162 p1 = __floats2bfloat162_rn(v.z, v.w);
    __nv_bfloat16* d = dst + (size_t)row * dld + c4;
    *(__nv_bfloat162*)(d)     = p0;
    *(__nv_bfloat162*)(d + 2) = p1;
}

// ---------------------------------------------------------------------------
// bf16 NT GEMM via WMMA: C fp32 = A . B^T. 128x128x32, 8 warps.
// ---------------------------------------------------------------------------
#define TCM 128
#define TCN 128
#define TCK 32

__global__ __launch_bounds__(256, 2)
void wmma_gemm_nt(const __nv_bfloat16* __restrict__ A, int lda,
                  const __nv_bfloat16* __restrict__ B, int ldb,
                  float* __restrict__ C, int ldc, int K)
{
    __shared__ __nv_bfloat16 As[TCM][TCK + 8];
    __shared__ __nv_bfloat16 Bs[TCN][TCK + 8];

    const int tid  = threadIdx.x;
    const int warp = tid >> 5;
    const int wm   = warp >> 1;
    const int wn   = warp & 1;
    const int bm   = blockIdx.y * TCM;
    const int bn   = blockIdx.x * TCN;

    const int lr = tid >> 1;
    const int lc = (tid & 1) * 16;

    wmma::fragment<wmma::accumulator, 16, 16, 16, float> acc[2][4];
    #pragma unroll
    for (int i = 0; i < 2; i++)
        #pragma unroll
        for (int j = 0; j < 4; j++) wmma::fill_fragment(acc[i][j], 0.0f);

    for (int k0 = 0; k0 < K; k0 += TCK) {
        const float4* asrc = (const float4*)(A + (size_t)(bm + lr) * lda + k0 + lc);
        const float4* bsrc = (const float4*)(B + (size_t)(bn + lr) * ldb + k0 + lc);
        float4 av0 = asrc[0], av1 = asrc[1];
        float4 bv0 = bsrc[0], bv1 = bsrc[1];
        __syncthreads();
        *(float4*)&As[lr][lc]     = av0;
        *(float4*)&As[lr][lc + 8] = av1;
        *(float4*)&Bs[lr][lc]     = bv0;
        *(float4*)&Bs[lr][lc + 8] = bv1;
        __syncthreads();

        #pragma unroll
        for (int kk = 0; kk < TCK; kk += 16) {
            wmma::fragment<wmma::matrix_a, 16, 16, 16, __nv_bfloat16, wmma::row_major> af[2];
            wmma::fragment<wmma::matrix_b, 16, 16, 16, __nv_bfloat16, wmma::col_major> bf[4];
            #pragma unroll
            for (int i = 0; i < 2; i++)
                wmma::load_matrix_sync(af[i], &As[wm * 32 + i * 16][kk], TCK + 8);
            #pragma unroll
            for (int j = 0; j < 4; j++)
                wmma::load_matrix_sync(bf[j], &Bs[wn * 64 + j * 16][kk], TCK + 8);
            #pragma unroll
            for (int i = 0; i < 2; i++)
                #pragma unroll
                for (int j = 0; j < 4; j++)
                    wmma::mma_sync(acc[i][j], af[i], bf[j], acc[i][j]);
        }
    }

    #pragma unroll
    for (int i = 0; i < 2; i++)
        #pragma unroll
        for (int j = 0; j < 4; j++)
            wmma::store_matrix_sync(
                &C[(size_t)(bm + wm * 32 + i * 16) * ldc + bn + wn * 64 + j * 16],
                acc[i][j], ldc, wmma::mem_row_major);
}

// ---------------------------------------------------------------------------
// H = gelu(H + bias[col]) over [BTOK, DHID].
// ---------------------------------------------------------------------------
__global__ void bias_gelu(float* __restrict__ H, const float* __restrict__ bias)
{
    int idx = blockIdx.x * blockDim.x + threadIdx.x;
    int col4 = (idx & (DHID / 4 - 1)) * 4;
    size_t off = (size_t)idx * 4;
    float4 v = *(float4*)(H + off);
    v.x = gelu_f(v.x + bias[col4 + 0]);
    v.y = gelu_f(v.y + bias[col4 + 1]);
    v.z = gelu_f(v.z + bias[col4 + 2]);
    v.w = gelu_f(v.w + bias[col4 + 3]);
    *(float4*)(H + off) = v;
}

// ---------------------------------------------------------------------------
// Approximate top-NCAND candidate selection per row (indices only).
// ---------------------------------------------------------------------------
__global__ __launch_bounds__(256)
void topk_cand(const float* __restrict__ sim, int* __restrict__ cand)
{
    __shared__ float vals[NSLOT];
    __shared__ float rmax[256];
    __shared__ int   ridx[256];

    const int t   = blockIdx.x;
    const int tid = threadIdx.x;
    const float* row = sim + (size_t)t * NSLOT;

    for (int i = tid; i < NSLOT; i += 256) vals[i] = row[i];
    __syncthreads();

    const float NEG_INF = __int_as_float(0xff800000);

    for (int it = 0; it < NCAND; it++) {
        float best = NEG_INF;
        int   bi   = 1 << 30;
        for (int i = tid; i < NSLOT; i += 256) {
            float v = vals[i];
            if (v > best) { best = v; bi = i; }
        }
        rmax[tid] = best; ridx[tid] = bi;
        __syncthreads();
        for (int st = 128; st > 0; st >>= 1) {
            if (tid < st) {
                float v2 = rmax[tid + st]; int i2 = ridx[tid + st];
                if (v2 > rmax[tid] || (v2 == rmax[tid] && i2 < ridx[tid])) {
                    rmax[tid] = v2; ridx[tid] = i2;
                }
            }
            __syncthreads();
        }
        if (tid == 0) {
            cand[(size_t)t * NCAND + it] = ridx[0];
            vals[ridx[0]] = NEG_INF;
        }
        __syncthreads();
    }
}

// ---------------------------------------------------------------------------
// Exact rescore of NCAND candidates per row (scheme-g serial chain per dot,
// RN divide), then exact top-32 with jax tie-break + softmax.
// Block = 64 threads (one per candidate), grid = BTOK.
// ---------------------------------------------------------------------------
__global__ __launch_bounds__(64)
void rescore_topk(const float* __restrict__ Q, const float* __restrict__ MK,
                  const int* __restrict__ cand,
                  float* __restrict__ w_out, int* __restrict__ idx_out,
                  float* __restrict__ dout_w, float* __restrict__ dout_idx)
{
    __shared__ float sq[DMODEL];
    __shared__ float vals64[NCAND];
    __shared__ int   slot64[NCAND];
    __shared__ float tv[KTOP];
    __shared__ int   ti[KTOP];

    const int t   = blockIdx.x;
    const int tid = threadIdx.x;

    // stage q row
    const float4* qr = (const float4*)(Q + (size_t)t * DMODEL);
    #pragma unroll
    for (int i = tid; i < DMODEL / 4; i += 64)
        *(float4*)&sq[i * 4] = qr[i];

    int slot = cand[(size_t)t * NCAND + tid];
    slot64[tid] = slot;
    __syncthreads();

    // exact scheme-g dot: ascending serial FMA chain, folds at 32 + n*336
    const float* krow = MK + (size_t)slot * DMODEL;
    float tot = 0.0f, chk = 0.0f;
    int nf = PEEL;
    for (int k0 = 0; k0 < DMODEL; k0 += 4) {
        float4 kv = *(const float4*)(krow + k0);
        chk = __fmaf_rn(sq[k0 + 0], kv.x, chk);
        chk = __fmaf_rn(sq[k0 + 1], kv.y, chk);
        chk = __fmaf_rn(sq[k0 + 2], kv.z, chk);
        chk = __fmaf_rn(sq[k0 + 3], kv.w, chk);
        if (k0 + 4 == nf) {
            tot = __fadd_rn(tot, chk);
            chk = 0.0f;
            nf += KC;
        }
    }
    vals64[tid] = __fdiv_rn(tot, __fsqrt_rn(2048.0f));
    __syncthreads();

    const float NEG_INF = __int_as_float(0xff800000);

    // warp 0: iterative top-32 with jax tie-break (lower slot on equal value)
    if (tid < 32) {
        for (int it = 0; it < KTOP; it++) {
            float v1 = vals64[tid],     v2 = vals64[tid + 32];
            int   s1 = slot64[tid],     s2 = slot64[tid + 32];
            int   p1 = tid,             p2 = tid + 32;
            float bv; int bs, bp;
            if (v2 > v1 || (v2 == v1 && s2 < s1)) { bv = v2; bs = s2; bp = p2; }
            else                                   { bv = v1; bs = s1; bp = p1; }
            #pragma unroll
            for (int o = 16; o > 0; o >>= 1) {
                float ov = __shfl_xor_sync(0xffffffffu, bv, o);
                int   os = __shfl_xor_sync(0xffffffffu, bs, o);
                int   op = __shfl_xor_sync(0xffffffffu, bp, o);
                if (ov > bv || (ov == bv && os < bs)) { bv = ov; bs = os; bp = op; }
            }
            if (tid == 0) {
                tv[it] = bv;
                ti[it] = bs;
                vals64[bp] = NEG_INF;
            }
            __syncwarp();
        }

        // softmax over top-32
        float e = expf(tv[tid] - tv[0]);
        float ssum = e;
        #pragma unroll
        for (int o = 16; o > 0; o >>= 1) ssum += __shfl_xor_sync(0xffffffffu, ssum, o);
        float w = e / ssum;
        size_t o = (size_t)t * KTOP + tid;
        w_out[o]   = w;
        idx_out[o] = ti[tid];
        if (dout_w)   dout_w[o]   = w;
        if (dout_idx) dout_idx[o] = (float)ti[tid];
    }
}

// ---------------------------------------------------------------------------
// retrieved[t,:] = sum_k w[t,k] * mem_values[idx[t,k], :]. One block/token.
// ---------------------------------------------------------------------------
__global__ __launch_bounds__(256)
void gather_wsum(const float* __restrict__ V,
                 const float* __restrict__ w, const int* __restrict__ idx,
                 float* __restrict__ outr)
{
    const int t   = blockIdx.x;
    const int tid = threadIdx.x;
    __shared__ float sw[KTOP];
    __shared__ int   si[KTOP];
    if (tid < KTOP) {
        sw[tid] = w[(size_t)t * KTOP + tid];
        si[tid] = idx[(size_t)t * KTOP + tid];
    }
    __syncthreads();

    float4 acc0 = make_float4(0.f, 0.f, 0.f, 0.f);
    float4 acc1 = make_float4(0.f, 0.f, 0.f, 0.f);
    #pragma unroll 4
    for (int k = 0; k < KTOP; k++) {
        const float4* vr = (const float4*)(V + (size_t)si[k] * DMODEL);
        float wk = sw[k];
        float4 v0 = vr[tid];
        float4 v1 = vr[tid + 256];
        acc0.x = fmaf(wk, v0.x, acc0.x); acc0.y = fmaf(wk, v0.y, acc0.y);
        acc0.z = fmaf(wk, v0.z, acc0.z); acc0.w = fmaf(wk, v0.w, acc0.w);
        acc1.x = fmaf(wk, v1.x, acc1.x); acc1.y = fmaf(wk, v1.y, acc1.y);
        acc1.z = fmaf(wk, v1.z, acc1.z); acc1.w = fmaf(wk, v1.w, acc1.w);
    }
    float4* orow = (float4*)(outr + (size_t)t * DMODEL);
    orow[tid]       = acc0;
    orow[tid + 256] = acc1;
}

// ---------------------------------------------------------------------------
// gate = sigmoid(h . wg2 + bg2); out = x + gate * R. One block/token.
// ---------------------------------------------------------------------------
__global__ __launch_bounds__(256)
void gate_output(const float* __restrict__ x, const float* __restrict__ R,
                 const float* __restrict__ H, const float* __restrict__ wg2,
                 const float* __restrict__ bg2, float* __restrict__ out)
{
    const int t   = blockIdx.x;
    const int tid = threadIdx.x;

    const float4* hr = (const float4*)(H + (size_t)t * DHID);
    const float4* gr = (const float4*)wg2;
    float4 hv = hr[tid];
    float4 gv = gr[tid];
    float p = hv.x * gv.x + hv.y * gv.y + hv.z * gv.z + hv.w * gv.w;

    __shared__ float red[256];
    red[tid] = p;
    __syncthreads();
    for (int st = 128; st > 0; st >>= 1) {
        if (tid < st) red[tid] += red[tid + st];
        __syncthreads();
    }
    __shared__ float gate_s;
    if (tid == 0) gate_s = 1.0f / (1.0f + expf(-(red[0] + bg2[0])));
    __syncthreads();
    float g = gate_s;

    const float4* xr = (const float4*)(x + (size_t)t * DMODEL);
    const float4* rr = (const float4*)(R + (size_t)t * DMODEL);
    float4* orow = (float4*)(out + (size_t)t * DMODEL);
    #pragma unroll
    for (int p4 = tid; p4 < DMODEL / 4; p4 += 256) {
        float4 xv = xr[p4], rv = rr[p4], ov;
        ov.x = xv.x + g * rv.x; ov.y = xv.y + g * rv.y;
        ov.z = xv.z + g * rv.z; ov.w = xv.w + g * rv.w;
        orow[p4] = ov;
    }
}

// ---------------------------------------------------------------------------
extern "C" void kernel_launch(void* const* d_in, const int* in_sizes, int n_in,
                              void* d_out, int out_size)
{
    const float* x   = (const float*)d_in[0];
    const float* mk  = (const float*)d_in[1];
    const float* mv  = (const float*)d_in[2];
    const float* wq  = (const float*)d_in[3];
    const float* wo  = (const float*)d_in[4];
    const float* wg1 = (const float*)d_in[5];
    const float* bg1 = (const float*)d_in[6];
    const float* wg2 = (const float*)d_in[7];
    const float* bg2 = (const float*)d_in[8];
    float* out = (float*)d_out;

    float *Q, *S, *RT, *R, *H, *W; int *IDX, *C64;
    __nv_bfloat16 *XRB, *RTB, *QB, *MKB, *WOB, *WG1B;
    cudaGetSymbolAddress((void**)&Q,    g_Q);
    cudaGetSymbolAddress((void**)&S,    g_sim);
    cudaGetSymbolAddress((void**)&RT,   g_retr);
    cudaGetSymbolAddress((void**)&R,    g_R);
    cudaGetSymbolAddress((void**)&H,    g_h);
    cudaGetSymbolAddress((void**)&W,    g_w);
    cudaGetSymbolAddress((void**)&IDX,  g_idx);
    cudaGetSymbolAddress((void**)&C64,  g_c64);
    cudaGetSymbolAddress((void**)&XRB,  g_xRbf);
    cudaGetSymbolAddress((void**)&RTB,  g_rtbf);
    cudaGetSymbolAddress((void**)&QB,   g_qbf);
    cudaGetSymbolAddress((void**)&MKB,  g_mkbf);
    cudaGetSymbolAddress((void**)&WOB,  g_wobf);
    cudaGetSymbolAddress((void**)&WG1B, g_wg1bf);

    float* dout_w   = nullptr;
    float* dout_idx = nullptr;
    const size_t out_elems = (size_t)BTOK * DMODEL;
    const size_t aux_elems = (size_t)BTOK * KTOP;
    if ((size_t)out_size >= out_elems + 2 * aux_elems) {
        dout_w   = out + out_elems;
        dout_idx = out + out_elems + aux_elems;
    }

    dim3 blk(256);

    // weight/input converts
    {
        int totw = DMODEL * DMODEL / 4;
        f32_to_bf16_2d<<<(totw + 255) / 256, blk>>>(wo, DMODEL, WOB, DMODEL,
                                                    DMODEL, DMODEL);
        int totg = DHID * 2 * DMODEL / 4;
        f32_to_bf16_2d<<<(totg + 255) / 256, blk>>>(wg1, 2 * DMODEL, WG1B,
                                                    2 * DMODEL, DHID, 2 * DMODEL);
        int totx = BTOK * DMODEL / 4;
        f32_to_bf16_2d<<<(totx + 255) / 256, blk>>>(x, DMODEL, XRB, 2 * DMODEL,
                                                    BTOK, DMODEL);
        int totk = NSLOT * DMODEL / 4;
        f32_to_bf16_2d<<<(totk + 255) / 256, blk>>>(mk, DMODEL, MKB, DMODEL,
                                                    NSLOT, DMODEL);
    }

    // 1) Q = X @ Wq^T  — scheme g (BIT-EXACT)
    sgemm_nt_exact2<<<dim3(DMODEL / 64, BTOK / 128), blk>>>(
        x, DMODEL, wq, DMODEL, Q, DMODEL, DMODEL);

    // 2) approx sim = Q.bf16 @ mem_keys.bf16^T  (tensor cores; unscaled)
    {
        int totq = BTOK * DMODEL / 4;
        f32_to_bf16_2d<<<(totq + 255) / 256, blk>>>(Q, DMODEL, QB, DMODEL,
                                                    BTOK, DMODEL);
        wmma_gemm_nt<<<dim3(NSLOT / TCN, BTOK / TCM), blk>>>(
            QB, DMODEL, MKB, DMODEL, S, NSLOT, DMODEL);
    }

    // 3) candidate top-64 (approx)
    topk_cand<<<BTOK, 256>>>(S, C64);

    // 4) exact rescore (scheme g per-dot) + top-32 + softmax
    rescore_topk<<<BTOK, 64>>>(Q, mk, C64, W, IDX, dout_w, dout_idx);

    // 5) gather + weighted sum
    gather_wsum<<<BTOK, 256>>>(mv, W, IDX, RT);

    // 6) R = retrieved @ Wo^T  — bf16 tensor cores
    {
        int tot = BTOK * DMODEL / 4;
        f32_to_bf16_2d<<<(tot + 255) / 256, blk>>>(RT, DMODEL, RTB, DMODEL,
                                                   BTOK, DMODEL);
        wmma_gemm_nt<<<dim3(DMODEL / TCN, BTOK / TCM), blk>>>(
            RTB, DMODEL, WOB, DMODEL, R, DMODEL, DMODEL);
    }

    // 7) h = gelu([x|R] @ Wg1^T + bg1) — single K=4096 bf16 GEMM
    {
        int tot = BTOK * DMODEL / 4;
        f32_to_bf16_2d<<<(tot + 255) / 256, blk>>>(R, DMODEL, XRB + DMODEL,
                                                   2 * DMODEL, BTOK, DMODEL);
        wmma_gemm_nt<<<dim3(DHID / TCN, BTOK / TCM), blk>>>(
            XRB, 2 * DMODEL, WG1B, 2 * DMODEL, H, DHID, 2 * DMODEL);
        int toth = BTOK * DHID / 4;
        bias_gelu<<<(toth + 255) / 256, blk>>>(H, bg1);
    }

    // 8) gate + residual output
    gate_output<<<BTOK, 256>>>(x, R, H, wg2, bg2, out);
}

// round 17
// speedup vs baseline: 2.0236x; 1.0348x over previous
#include <cuda_runtime.h>
#include <cuda_bf16.h>
#include <mma.h>
#include <math.h>
#include <stdint.h>

using namespace nvcuda;

// Problem constants
#define BTOK   8192
#define DMODEL 2048
#define NSLOT  4096
#define KTOP   32
#define NCAND  64
#define DHID   1024

// Reference accumulation (scheme g, VERIFIED): remainder-first kc=336 panels,
// ascending serial FMA chains, folds at kend in {32,368,704,1040,1376,1712,2048}.
#define KC 336
#define PEEL 32

// Scratch (device globals)
static __device__ float g_Q   [(size_t)BTOK * DMODEL];
static __device__ float g_sim [(size_t)BTOK * NSLOT];
static __device__ float g_retr[(size_t)BTOK * DMODEL];
static __device__ float g_R   [(size_t)BTOK * DMODEL];
static __device__ float g_h   [(size_t)BTOK * DHID];
static __device__ float g_w   [BTOK * KTOP];
static __device__ int   g_idx [BTOK * KTOP];
static __device__ int   g_c64 [(size_t)BTOK * NCAND];
// bf16 staging
static __device__ __nv_bfloat16 g_xRbf [(size_t)BTOK * (2 * DMODEL)];
static __device__ __nv_bfloat16 g_rtbf [(size_t)BTOK * DMODEL];
static __device__ __nv_bfloat16 g_qbf  [(size_t)BTOK * DMODEL];
static __device__ __nv_bfloat16 g_mkbf [(size_t)NSLOT * DMODEL];
static __device__ __nv_bfloat16 g_wobf [(size_t)DMODEL * DMODEL];
static __device__ __nv_bfloat16 g_wg1bf[(size_t)DHID * 2 * DMODEL];

__device__ __forceinline__ float gelu_f(float v) {
    return 0.5f * v * (1.0f + erff(v * 0.70710678118654752440f));
}

#define CP_ASYNC16(dst_s32, src) \
    asm volatile("cp.async.cg.shared.global [%0], [%1], 16;\n" \
                 :: "r"(dst_s32), "l"(src))
#define CP_COMMIT() asm volatile("cp.async.commit_group;\n")
#define CP_WAIT(n)  asm volatile("cp.async.wait_group %0;\n" :: "n"(n))

// ---------------------------------------------------------------------------
// Exact (scheme g) NT SGEMM for Q. BIT-IDENTICAL per-element arithmetic:
// ascending serial FMA chain, folds at kend = 32, 368, 704, ..., 2048.
// BK=16 (all fold boundaries are multiples of 16). Epilogue also writes bf16.
// BM=128, BN=64, 256 threads, 8x4 micro.
// ---------------------------------------------------------------------------
__global__ __launch_bounds__(256, 2)
void sgemm_nt_exact3(const float* __restrict__ A, int lda,
                     const float* __restrict__ B, int ldb,
                     float* __restrict__ C, int ldc,
                     __nv_bfloat16* __restrict__ Cbf, int K)
{
    const int BM = 128, BN = 64, BK = 16;
    __shared__ float As[BK][BM + 4];
    __shared__ float Bs[BK][BN + 4];

    const int tid = threadIdx.x;
    const int bm  = blockIdx.y * BM;
    const int bn  = blockIdx.x * BN;
    const int lrA = tid >> 1;           // 0..127
    const int lcA = (tid & 1) * 8;      // 0,8
    const int lrB = tid >> 2;           // 0..63
    const int lcB = (tid & 3) * 4;      // 0,4,8,12

    const float* Ap = A + (size_t)(bm + lrA) * lda + lcA;
    const float* Bp = B + (size_t)(bn + lrB) * ldb + lcB;

    const int tx = tid & 15;
    const int ty = tid >> 4;

    float tot[8][4], chk[8][4];
    #pragma unroll
    for (int i = 0; i < 8; i++)
        #pragma unroll
        for (int j = 0; j < 4; j++) { tot[i][j] = 0.0f; chk[i][j] = 0.0f; }

    for (int k0 = 0; k0 < K; k0 += BK) {
        float4 a0 = *(const float4*)(Ap + k0);
        float4 a1 = *(const float4*)(Ap + k0 + 4);
        float4 b0 = *(const float4*)(Bp + k0);
        __syncthreads();
        As[lcA + 0][lrA] = a0.x; As[lcA + 1][lrA] = a0.y;
        As[lcA + 2][lrA] = a0.z; As[lcA + 3][lrA] = a0.w;
        As[lcA + 4][lrA] = a1.x; As[lcA + 5][lrA] = a1.y;
        As[lcA + 6][lrA] = a1.z; As[lcA + 7][lrA] = a1.w;
        Bs[lcB + 0][lrB] = b0.x; Bs[lcB + 1][lrB] = b0.y;
        Bs[lcB + 2][lrB] = b0.z; Bs[lcB + 3][lrB] = b0.w;
        __syncthreads();

        #pragma unroll
        for (int k = 0; k < BK; k++) {
            float ra[8], rb[4];
            *(float4*)(ra)     = *(const float4*)&As[k][ty * 8];
            *(float4*)(ra + 4) = *(const float4*)&As[k][ty * 8 + 4];
            *(float4*)(rb)     = *(const float4*)&Bs[k][tx * 4];
            #pragma unroll
            for (int i = 0; i < 8; i++)
                #pragma unroll
                for (int j = 0; j < 4; j++)
                    chk[i][j] = __fmaf_rn(ra[i], rb[j], chk[i][j]);
        }

        int kend = k0 + BK;
        bool fold = (kend == PEEL) ||
                    (kend > PEEL && ((kend - PEEL) % KC) == 0);
        if (fold) {
            #pragma unroll
            for (int i = 0; i < 8; i++)
                #pragma unroll
                for (int j = 0; j < 4; j++) {
                    tot[i][j] = __fadd_rn(tot[i][j], chk[i][j]);
                    chk[i][j] = 0.0f;
                }
        }
    }

    #pragma unroll
    for (int i = 0; i < 8; i++) {
        size_t row = (size_t)(bm + ty * 8 + i);
        float4 v;
        v.x = tot[i][0]; v.y = tot[i][1]; v.z = tot[i][2]; v.w = tot[i][3];
        *(float4*)(C + row * (size_t)ldc + bn + tx * 4) = v;
        __nv_bfloat162 p0 = __floats2bfloat162_rn(v.x, v.y);
        __nv_bfloat162 p1 = __floats2bfloat162_rn(v.z, v.w);
        __nv_bfloat16* d = Cbf + row * (size_t)ldc + bn + tx * 4;
        *(__nv_bfloat162*)(d)     = p0;
        *(__nv_bfloat162*)(d + 2) = p1;
    }
}

// ---------------------------------------------------------------------------
// fp32 -> bf16 2D conversion.
// ---------------------------------------------------------------------------
__global__ void f32_to_bf16_2d(const float* __restrict__ src, int sld,
                               __nv_bfloat16* __restrict__ dst, int dld,
                               int rows, int cols)
{
    int idx = blockIdx.x * blockDim.x + threadIdx.x;
    int total = rows * (cols >> 2);
    if (idx >= total) return;
    int row = idx / (cols >> 2);
    int c4  = (idx - row * (cols >> 2)) << 2;
    float4 v = *(const float4*)(src + (size_t)row * sld + c4);
    __nv_bfloat162 p0 = __floats2bfloat162_rn(v.x, v.y);
    __nv_bfloat162 p1 = __floats2bfloat162_rn(v.z, v.w);
    __nv_bfloat16* d = dst + (size_t)row * dld + c4;
    *(__nv_bfloat162*)(d)     = p0;
    *(__nv_bfloat162*)(d + 2) = p1;
}

// ---------------------------------------------------------------------------
// bf16 NT GEMM via WMMA, double-buffered cp.async pipeline.
// C fp32 = A . B^T. 128x128x32, 8 warps (4x2), warp tile 32x64.
// ---------------------------------------------------------------------------
#define TCM 128
#define TCN 128
#define TCK 32
#define SPITCH (TCK + 8)   // bf16 elems per smem row (80 bytes, 16B aligned)

__global__ __launch_bounds__(256, 2)
void wmma_gemm_db(const __nv_bfloat16* __restrict__ A, int lda,
                  const __nv_bfloat16* __restrict__ B, int ldb,
                  float* __restrict__ C, int ldc, int K)
{
    __shared__ __nv_bfloat16 As[2][TCM][SPITCH];
    __shared__ __nv_bfloat16 Bs[2][TCN][SPITCH];

    const int tid  = threadIdx.x;
    const int warp = tid >> 5;
    const int wm   = warp >> 1;
    const int wn   = warp & 1;
    const int bm   = blockIdx.y * TCM;
    const int bn   = blockIdx.x * TCN;

    const int lr = tid >> 1;          // 0..127
    const int lc = (tid & 1) * 16;    // 0 or 16

    const __nv_bfloat16* Ag = A + (size_t)(bm + lr) * lda + lc;
    const __nv_bfloat16* Bg = B + (size_t)(bn + lr) * ldb + lc;

    uint32_t asA0 = (uint32_t)__cvta_generic_to_shared(&As[0][lr][lc]);
    uint32_t asA1 = (uint32_t)__cvta_generic_to_shared(&As[1][lr][lc]);
    uint32_t asB0 = (uint32_t)__cvta_generic_to_shared(&Bs[0][lr][lc]);
    uint32_t asB1 = (uint32_t)__cvta_generic_to_shared(&Bs[1][lr][lc]);

    wmma::fragment<wmma::accumulator, 16, 16, 16, float> acc[2][4];
    #pragma unroll
    for (int i = 0; i < 2; i++)
        #pragma unroll
        for (int j = 0; j < 4; j++) wmma::fill_fragment(acc[i][j], 0.0f);

    const int ntiles = K / TCK;

    // prologue: stage 0
    CP_ASYNC16(asA0,      Ag);
    CP_ASYNC16(asA0 + 16, Ag + 8);
    CP_ASYNC16(asB0,      Bg);
    CP_ASYNC16(asB0 + 16, Bg + 8);
    CP_COMMIT();

    for (int it = 0; it < ntiles; it++) {
        int cur = it & 1;
        // prefetch next stage
        if (it + 1 < ntiles) {
            const __nv_bfloat16* An = Ag + (size_t)(it + 1) * TCK;
            const __nv_bfloat16* Bn = Bg + (size_t)(it + 1) * TCK;
            uint32_t dA = (cur ? asA0 : asA1);
            uint32_t dB = (cur ? asB0 : asB1);
            CP_ASYNC16(dA,      An);
            CP_ASYNC16(dA + 16, An + 8);
            CP_ASYNC16(dB,      Bn);
            CP_ASYNC16(dB + 16, Bn + 8);
            CP_COMMIT();
            CP_WAIT(1);
        } else {
            CP_WAIT(0);
        }
        __syncthreads();

        #pragma unroll
        for (int kk = 0; kk < TCK; kk += 16) {
            wmma::fragment<wmma::matrix_a, 16, 16, 16, __nv_bfloat16, wmma::row_major> af[2];
            wmma::fragment<wmma::matrix_b, 16, 16, 16, __nv_bfloat16, wmma::col_major> bf[4];
            #pragma unroll
            for (int i = 0; i < 2; i++)
                wmma::load_matrix_sync(af[i], &As[cur][wm * 32 + i * 16][kk], SPITCH);
            #pragma unroll
            for (int j = 0; j < 4; j++)
                wmma::load_matrix_sync(bf[j], &Bs[cur][wn * 64 + j * 16][kk], SPITCH);
            #pragma unroll
            for (int i = 0; i < 2; i++)
                #pragma unroll
                for (int j = 0; j < 4; j++)
                    wmma::mma_sync(acc[i][j], af[i], bf[j], acc[i][j]);
        }
        __syncthreads();
    }

    #pragma unroll
    for (int i = 0; i < 2; i++)
        #pragma unroll
        for (int j = 0; j < 4; j++)
            wmma::store_matrix_sync(
                &C[(size_t)(bm + wm * 32 + i * 16) * ldc + bn + wn * 64 + j * 16],
                acc[i][j], ldc, wmma::mem_row_major);
}

// ---------------------------------------------------------------------------
// H = gelu(H + bias[col]) over [BTOK, DHID].
// ---------------------------------------------------------------------------
__global__ void bias_gelu(float* __restrict__ H, const float* __restrict__ bias)
{
    int idx = blockIdx.x * blockDim.x + threadIdx.x;
    int col4 = (idx & (DHID / 4 - 1)) * 4;
    size_t off = (size_t)idx * 4;
    float4 v = *(float4*)(H + off);
    v.x = gelu_f(v.x + bias[col4 + 0]);
    v.y = gelu_f(v.y + bias[col4 + 1]);
    v.z = gelu_f(v.z + bias[col4 + 2]);
    v.w = gelu_f(v.w + bias[col4 + 3]);
    *(float4*)(H + off) = v;
}

// ---------------------------------------------------------------------------
// Approximate top-NCAND candidate selection per row (indices only).
// ---------------------------------------------------------------------------
__global__ __launch_bounds__(256)
void topk_cand(const float* __restrict__ sim, int* __restrict__ cand)
{
    __shared__ float vals[NSLOT];
    __shared__ float rmax[256];
    __shared__ int   ridx[256];

    const int t   = blockIdx.x;
    const int tid = threadIdx.x;
    const float* row = sim + (size_t)t * NSLOT;

    for (int i = tid; i < NSLOT; i += 256) vals[i] = row[i];
    __syncthreads();

    const float NEG_INF = __int_as_float(0xff800000);

    for (int it = 0; it < NCAND; it++) {
        float best = NEG_INF;
        int   bi   = 1 << 30;
        for (int i = tid; i < NSLOT; i += 256) {
            float v = vals[i];
            if (v > best) { best = v; bi = i; }
        }
        rmax[tid] = best; ridx[tid] = bi;
        __syncthreads();
        for (int st = 128; st > 0; st >>= 1) {
            if (tid < st) {
                float v2 = rmax[tid + st]; int i2 = ridx[tid + st];
                if (v2 > rmax[tid] || (v2 == rmax[tid] && i2 < ridx[tid])) {
                    rmax[tid] = v2; ridx[tid] = i2;
                }
            }
            __syncthreads();
        }
        if (tid == 0) {
            cand[(size_t)t * NCAND + it] = ridx[0];
            vals[ridx[0]] = NEG_INF;
        }
        __syncthreads();
    }
}

// ---------------------------------------------------------------------------
// Exact rescore (scheme-g chain per dot, RN divide) + top-32 + softmax.
// ---------------------------------------------------------------------------
__global__ __launch_bounds__(64)
void rescore_topk(const float* __restrict__ Q, const float* __restrict__ MK,
                  const int* __restrict__ cand,
                  float* __restrict__ w_out, int* __restrict__ idx_out,
                  float* __restrict__ dout_w, float* __restrict__ dout_idx)
{
    __shared__ float sq[DMODEL];
    __shared__ float vals64[NCAND];
    __shared__ int   slot64[NCAND];
    __shared__ float tv[KTOP];
    __shared__ int   ti[KTOP];

    const int t   = blockIdx.x;
    const int tid = threadIdx.x;

    const float4* qr = (const float4*)(Q + (size_t)t * DMODEL);
    #pragma unroll
    for (int i = tid; i < DMODEL / 4; i += 64)
        *(float4*)&sq[i * 4] = qr[i];

    int slot = cand[(size_t)t * NCAND + tid];
    slot64[tid] = slot;
    __syncthreads();

    const float* krow = MK + (size_t)slot * DMODEL;
    float tot = 0.0f, chk = 0.0f;
    int nf = PEEL;
    for (int k0 = 0; k0 < DMODEL; k0 += 4) {
        float4 kv = *(const float4*)(krow + k0);
        chk = __fmaf_rn(sq[k0 + 0], kv.x, chk);
        chk = __fmaf_rn(sq[k0 + 1], kv.y, chk);
        chk = __fmaf_rn(sq[k0 + 2], kv.z, chk);
        chk = __fmaf_rn(sq[k0 + 3], kv.w, chk);
        if (k0 + 4 == nf) {
            tot = __fadd_rn(tot, chk);
            chk = 0.0f;
            nf += KC;
        }
    }
    vals64[tid] = __fdiv_rn(tot, __fsqrt_rn(2048.0f));
    __syncthreads();

    const float NEG_INF = __int_as_float(0xff800000);

    if (tid < 32) {
        for (int it = 0; it < KTOP; it++) {
            float v1 = vals64[tid],     v2 = vals64[tid + 32];
            int   s1 = slot64[tid],     s2 = slot64[tid + 32];
            int   p1 = tid,             p2 = tid + 32;
            float bv; int bs, bp;
            if (v2 > v1 || (v2 == v1 && s2 < s1)) { bv = v2; bs = s2; bp = p2; }
            else                                   { bv = v1; bs = s1; bp = p1; }
            #pragma unroll
            for (int o = 16; o > 0; o >>= 1) {
                float ov = __shfl_xor_sync(0xffffffffu, bv, o);
                int   os = __shfl_xor_sync(0xffffffffu, bs, o);
                int   op = __shfl_xor_sync(0xffffffffu, bp, o);
                if (ov > bv || (ov == bv && os < bs)) { bv = ov; bs = os; bp = op; }
            }
            if (tid == 0) {
                tv[it] = bv;
                ti[it] = bs;
                vals64[bp] = NEG_INF;
            }
            __syncwarp();
        }

        float e = expf(tv[tid] - tv[0]);
        float ssum = e;
        #pragma unroll
        for (int o = 16; o > 0; o >>= 1) ssum += __shfl_xor_sync(0xffffffffu, ssum, o);
        float w = e / ssum;
        size_t o = (size_t)t * KTOP + tid;
        w_out[o]   = w;
        idx_out[o] = ti[tid];
        if (dout_w)   dout_w[o]   = w;
        if (dout_idx) dout_idx[o] = (float)ti[tid];
    }
}

// ---------------------------------------------------------------------------
// retrieved[t,:] = sum_k w[t,k] * mem_values[idx[t,k], :].
// ---------------------------------------------------------------------------
__global__ __launch_bounds__(256)
void gather_wsum(const float* __restrict__ V,
                 const float* __restrict__ w, const int* __restrict__ idx,
                 float* __restrict__ outr)
{
    const int t   = blockIdx.x;
    const int tid = threadIdx.x;
    __shared__ float sw[KTOP];
    __shared__ int   si[KTOP];
    if (tid < KTOP) {
        sw[tid] = w[(size_t)t * KTOP + tid];
        si[tid] = idx[(size_t)t * KTOP + tid];
    }
    __syncthreads();

    float4 acc0 = make_float4(0.f, 0.f, 0.f, 0.f);
    float4 acc1 = make_float4(0.f, 0.f, 0.f, 0.f);
    #pragma unroll 4
    for (int k = 0; k < KTOP; k++) {
        const float4* vr = (const float4*)(V + (size_t)si[k] * DMODEL);
        float wk = sw[k];
        float4 v0 = vr[tid];
        float4 v1 = vr[tid + 256];
        acc0.x = fmaf(wk, v0.x, acc0.x); acc0.y = fmaf(wk, v0.y, acc0.y);
        acc0.z = fmaf(wk, v0.z, acc0.z); acc0.w = fmaf(wk, v0.w, acc0.w);
        acc1.x = fmaf(wk, v1.x, acc1.x); acc1.y = fmaf(wk, v1.y, acc1.y);
        acc1.z = fmaf(wk, v1.z, acc1.z); acc1.w = fmaf(wk, v1.w, acc1.w);
    }
    float4* orow = (float4*)(outr + (size_t)t * DMODEL);
    orow[tid]       = acc0;
    orow[tid + 256] = acc1;
}

// ---------------------------------------------------------------------------
// gate = sigmoid(h . wg2 + bg2); out = x + gate * R.
// ---------------------------------------------------------------------------
__global__ __launch_bounds__(256)
void gate_output(const float* __restrict__ x, const float* __restrict__ R,
                 const float* __restrict__ H, const float* __restrict__ wg2,
                 const float* __restrict__ bg2, float* __restrict__ out)
{
    const int t   = blockIdx.x;
    const int tid = threadIdx.x;

    const float4* hr = (const float4*)(H + (size_t)t * DHID);
    const float4* gr = (const float4*)wg2;
    float4 hv = hr[tid];
    float4 gv = gr[tid];
    float p = hv.x * gv.x + hv.y * gv.y + hv.z * gv.z + hv.w * gv.w;

    __shared__ float red[256];
    red[tid] = p;
    __syncthreads();
    for (int st = 128; st > 0; st >>= 1) {
        if (tid < st) red[tid] += red[tid + st];
        __syncthreads();
    }
    __shared__ float gate_s;
    if (tid == 0) gate_s = 1.0f / (1.0f + expf(-(red[0] + bg2[0])));
    __syncthreads();
    float g = gate_s;

    const float4* xr = (const float4*)(x + (size_t)t * DMODEL);
    const float4* rr = (const float4*)(R + (size_t)t * DMODEL);
    float4* orow = (float4*)(out + (size_t)t * DMODEL);
    #pragma unroll
    for (int p4 = tid; p4 < DMODEL / 4; p4 += 256) {
        float4 xv = xr[p4], rv = rr[p4], ov;
        ov.x = xv.x + g * rv.x; ov.y = xv.y + g * rv.y;
        ov.z = xv.z + g * rv.z; ov.w = xv.w + g * rv.w;
        orow[p4] = ov;
    }
}

// ---------------------------------------------------------------------------
extern "C" void kernel_launch(void* const* d_in, const int* in_sizes, int n_in,
                              void* d_out, int out_size)
{
    const float* x   = (const float*)d_in[0];
    const float* mk  = (const float*)d_in[1];
    const float* mv  = (const float*)d_in[2];
    const float* wq  = (const float*)d_in[3];
    const float* wo  = (const float*)d_in[4];
    const float* wg1 = (const float*)d_in[5];
    const float* bg1 = (const float*)d_in[6];
    const float* wg2 = (const float*)d_in[7];
    const float* bg2 = (const float*)d_in[8];
    float* out = (float*)d_out;

    float *Q, *S, *RT, *R, *H, *W; int *IDX, *C64;
    __nv_bfloat16 *XRB, *RTB, *QB, *MKB, *WOB, *WG1B;
    cudaGetSymbolAddress((void**)&Q,    g_Q);
    cudaGetSymbolAddress((void**)&S,    g_sim);
    cudaGetSymbolAddress((void**)&RT,   g_retr);
    cudaGetSymbolAddress((void**)&R,    g_R);
    cudaGetSymbolAddress((void**)&H,    g_h);
    cudaGetSymbolAddress((void**)&W,    g_w);
    cudaGetSymbolAddress((void**)&IDX,  g_idx);
    cudaGetSymbolAddress((void**)&C64,  g_c64);
    cudaGetSymbolAddress((void**)&XRB,  g_xRbf);
    cudaGetSymbolAddress((void**)&RTB,  g_rtbf);
    cudaGetSymbolAddress((void**)&QB,   g_qbf);
    cudaGetSymbolAddress((void**)&MKB,  g_mkbf);
    cudaGetSymbolAddress((void**)&WOB,  g_wobf);
    cudaGetSymbolAddress((void**)&WG1B, g_wg1bf);

    float* dout_w   = nullptr;
    float* dout_idx = nullptr;
    const size_t out_elems = (size_t)BTOK * DMODEL;
    const size_t aux_elems = (size_t)BTOK * KTOP;
    if ((size_t)out_size >= out_elems + 2 * aux_elems) {
        dout_w   = out + out_elems;
        dout_idx = out + out_elems + aux_elems;
    }

    dim3 blk(256);

    // converts
    {
        int totw = DMODEL * DMODEL / 4;
        f32_to_bf16_2d<<<(totw + 255) / 256, blk>>>(wo, DMODEL, WOB, DMODEL,
                                                    DMODEL, DMODEL);
        int totg = DHID * 2 * DMODEL / 4;
        f32_to_bf16_2d<<<(totg + 255) / 256, blk>>>(wg1, 2 * DMODEL, WG1B,
                                                    2 * DMODEL, DHID, 2 * DMODEL);
        int totx = BTOK * DMODEL / 4;
        f32_to_bf16_2d<<<(totx + 255) / 256, blk>>>(x, DMODEL, XRB, 2 * DMODEL,
                                                    BTOK, DMODEL);
        int totk = NSLOT * DMODEL / 4;
        f32_to_bf16_2d<<<(totk + 255) / 256, blk>>>(mk, DMODEL, MKB, DMODEL,
                                                    NSLOT, DMODEL);
    }

    // 1) Q = X @ Wq^T — scheme g (BIT-EXACT), fused bf16 output
    sgemm_nt_exact3<<<dim3(DMODEL / 64, BTOK / 128), blk>>>(
        x, DMODEL, wq, DMODEL, Q, DMODEL, QB, DMODEL);

    // 2) approx sim = Qbf @ MKbf^T (TC, double-buffered)
    wmma_gemm_db<<<dim3(NSLOT / TCN, BTOK / TCM), blk>>>(
        QB, DMODEL, MKB, DMODEL, S, NSLOT, DMODEL);

    // 3) candidate top-64 (approx)
    topk_cand<<<BTOK, 256>>>(S, C64);

    // 4) exact rescore + top-32 + softmax
    rescore_topk<<<BTOK, 64>>>(Q, mk, C64, W, IDX, dout_w, dout_idx);

    // 5) gather + weighted sum
    gather_wsum<<<BTOK, 256>>>(mv, W, IDX, RT);

    // 6) R = retrieved @ Wo^T — TC
    {
        int tot = BTOK * DMODEL / 4;
        f32_to_bf16_2d<<<(tot + 255) / 256, blk>>>(RT, DMODEL, RTB, DMODEL,
                                                   BTOK, DMODEL);
        wmma_gemm_db<<<dim3(DMODEL / TCN, BTOK / TCM), blk>>>(
            RTB, DMODEL, WOB, DMODEL, R, DMODEL, DMODEL);
    }

    // 7) h = gelu([x|R] @ Wg1^T + bg1) — single K=4096 TC GEMM
    {
        int tot = BTOK * DMODEL / 4;
        f32_to_bf16_2d<<<(tot + 255) / 256, blk>>>(R, DMODEL, XRB + DMODEL,
                                                   2 * DMODEL, BTOK, DMODEL);
        wmma_gemm_db<<<dim3(DHID / TCN, BTOK / TCM), blk>>>(
            XRB, 2 * DMODEL, WG1B, 2 * DMODEL, H, DHID, 2 * DMODEL);
        int toth = BTOK * DHID / 4;
        bias_gelu<<<(toth + 255) / 256, blk>>>(H, bg1);
    }

    // 8) gate + residual output
    gate_output<<<BTOK, 256>>>(x, R, H, wg2, bg2, out);
}